// round 6
// baseline (speedup 1.0000x reference)
#include <cuda_runtime.h>
#include <cuda_bf16.h>
#include <math.h>
#include <stdint.h>

#define MTOK 4096      // B*S
#define HID  2048
#define INTER 8192

// ======================= device scratch (no allocations) ====================
__device__ __nv_bfloat16 w_qkv_hi[(size_t)3*HID*HID], w_qkv_lo[(size_t)3*HID*HID];
__device__ __nv_bfloat16 w_o_hi[HID*HID],  w_o_lo[HID*HID];
__device__ __nv_bfloat16 w_gu_hi[(size_t)2*INTER*HID], w_gu_lo[(size_t)2*INTER*HID];
__device__ __nv_bfloat16 w_d_hi[(size_t)HID*INTER], w_d_lo[(size_t)HID*INTER];
__device__ __nv_bfloat16 a_x_hi[MTOK*HID],  a_x_lo[MTOK*HID];
__device__ __nv_bfloat16 a_at_hi[MTOK*HID], a_at_lo[MTOK*HID];
__device__ __nv_bfloat16 a_m_hi[(size_t)MTOK*INTER], a_m_lo[(size_t)MTOK*INTER];
__device__ __nv_bfloat16 qkv_hi[(size_t)MTOK*3*HID], qkv_lo[(size_t)MTOK*3*HID];
__device__ __nv_bfloat16 vt_hi[MTOK*HID], vt_lo[MTOK*HID];   // [b*16+h][hd][kv]
__device__ float s_h1[MTOK*HID];
__device__ float s_gu[(size_t)MTOK*2*INTER];

// ======================= helpers ============================================
__device__ __forceinline__ uint32_t smem_u32(const void* p) {
    uint32_t a;
    asm("{ .reg .u64 t; cvta.to.shared.u64 t, %1; cvt.u32.u64 %0, t; }" : "=r"(a) : "l"(p));
    return a;
}
__device__ __forceinline__ void cp16(uint32_t s, const void* g) {
    asm volatile("cp.async.cg.shared.global [%0], [%1], 16;" :: "r"(s), "l"(g));
}
#define CP_COMMIT() asm volatile("cp.async.commit_group;")
#define CP_WAIT(N)  asm volatile("cp.async.wait_group %0;" :: "n"(N))

__device__ __forceinline__ void mma_bf16(float* c, const uint32_t* a, const uint32_t* b) {
    asm volatile(
        "mma.sync.aligned.m16n8k16.row.col.f32.bf16.bf16.f32 "
        "{%0,%1,%2,%3}, {%4,%5,%6,%7}, {%8,%9}, {%0,%1,%2,%3};"
        : "+f"(c[0]), "+f"(c[1]), "+f"(c[2]), "+f"(c[3])
        : "r"(a[0]), "r"(a[1]), "r"(a[2]), "r"(a[3]), "r"(b[0]), "r"(b[1]));
}
__device__ __forceinline__ void ldsm4(uint32_t* r, uint32_t addr) {
    asm volatile("ldmatrix.sync.aligned.m8n8.x4.shared.b16 {%0,%1,%2,%3}, [%4];"
                 : "=r"(r[0]), "=r"(r[1]), "=r"(r[2]), "=r"(r[3]) : "r"(addr));
}
__device__ __forceinline__ void split2(float x, float y, uint32_t& hi, uint32_t& lo) {
    __nv_bfloat162 h;
    h.x = __float2bfloat16(x); h.y = __float2bfloat16(y);
    __nv_bfloat162 l;
    l.x = __float2bfloat16(x - __bfloat162float(h.x));
    l.y = __float2bfloat16(y - __bfloat162float(h.y));
    hi = *reinterpret_cast<uint32_t*>(&h);
    lo = *reinterpret_cast<uint32_t*>(&l);
}

// ======================= bf16x3 mma.sync GEMM (ldmatrix) ====================
// OM: 0 = fp32 out, 1 = fp32 out + residual, 2 = bf16 hi/lo out (scale cols<scaleN)
// BM=BN=128, BK=64, 256 threads (8 warps: 4 M x 2 N), double-buffered cp.async.
#define RB   144
#define TILE (128*RB)            // 18432
#define STG  (4*TILE)            // 73728: Ah, Al, Bh, Bl
#define GEMM_SMEM (2*STG)        // 147456

template<int OM>
__global__ __launch_bounds__(256) void gemm3bf(
    const __nv_bfloat16* __restrict__ Ahi, const __nv_bfloat16* __restrict__ Alo,
    const __nv_bfloat16* __restrict__ Bhi, const __nv_bfloat16* __restrict__ Blo,
    const float* __restrict__ R, float* __restrict__ C,
    __nv_bfloat16* __restrict__ Ch, __nv_bfloat16* __restrict__ Cl,
    float scale, int scaleN, int M, int N, int K)
{
    extern __shared__ char sm[];
    const uint32_t sbase = smem_u32(sm);

    const int tid = threadIdx.x;
    const int lane = tid & 31;
    const int wid = tid >> 5;
    const int g = lane >> 2, tig = lane & 3;
    const int warp_m = wid & 3;
    const int warp_n = wid >> 2;
    const int bm = blockIdx.y * 128;
    const int bn = blockIdx.x * 128;

    const int crow = tid >> 3;            // 0..31
    const int ccolB = (tid & 7) * 16;

    const int S = K >> 6;

    auto load_stage = [&](int s) {
        const uint32_t b = sbase + (uint32_t)(s & 1) * STG;
        const int k0 = s << 6;
        const size_t ga = ((size_t)(bm + crow) * K + k0) * 2 + ccolB;
        const size_t gb = ((size_t)(bn + crow) * K + k0) * 2 + ccolB;
        const size_t rstep = (size_t)32 * K * 2;
        const char* pah = (const char*)Ahi + ga;
        const char* pal = (const char*)Alo + ga;
        const char* pbh = (const char*)Bhi + gb;
        const char* pbl = (const char*)Blo + gb;
        #pragma unroll
        for (int i = 0; i < 4; i++) {
            const uint32_t so = (uint32_t)((crow + 32*i) * RB + ccolB);
            cp16(b + so,            pah); pah += rstep;
            cp16(b + TILE   + so,   pal); pal += rstep;
            cp16(b + 2*TILE + so,   pbh); pbh += rstep;
            cp16(b + 3*TILE + so,   pbl); pbl += rstep;
        }
        CP_COMMIT();
    };

    load_stage(0);
    if (S > 1) load_stage(1);

    float acc[2][8][4];
    #pragma unroll
    for (int mt = 0; mt < 2; mt++)
        #pragma unroll
        for (int nt = 0; nt < 8; nt++)
            #pragma unroll
            for (int e = 0; e < 4; e++) acc[mt][nt][e] = 0.f;

    // ldmatrix per-lane addresses:
    // lanes 0-7: rows 0-7 kblk0 | 8-15: rows 8-15 kblk0 | 16-23: rows 0-7 kblk1 | 24-31: rows 8-15 kblk1
    const int lr = lane & 15;
    const uint32_t lk = (uint32_t)(lane >> 4) * 16u;
    const uint32_t aAddr = sbase + (uint32_t)(warp_m*32 + lr) * RB + lk;
    const uint32_t bAddr = sbase + 2u*TILE + (uint32_t)(warp_n*64 + lr) * RB + lk;

    for (int s = 0; s < S; ++s) {
        if (s + 1 < S) { CP_WAIT(1); } else { CP_WAIT(0); }
        __syncthreads();
        const uint32_t st = (uint32_t)(s & 1) * STG;

        #pragma unroll
        for (int ks = 0; ks < 4; ++ks) {
            const uint32_t kb = (uint32_t)ks * 32u;

            uint32_t ah[2][4], al[2][4], bhf[8][2], blf[8][2];
            const uint32_t a0 = aAddr + st + kb;
            ldsm4(ah[0], a0);
            ldsm4(ah[1], a0 + 16u*RB);
            ldsm4(al[0], a0 + TILE);
            ldsm4(al[1], a0 + TILE + 16u*RB);

            const uint32_t b0 = bAddr + st + kb;
            #pragma unroll
            for (int p = 0; p < 4; p++) {
                uint32_t rh[4], rl[4];
                ldsm4(rh, b0 + (uint32_t)p*16u*RB);
                ldsm4(rl, b0 + (uint32_t)p*16u*RB + TILE);
                bhf[2*p][0]   = rh[0]; bhf[2*p+1][0] = rh[1];
                bhf[2*p][1]   = rh[2]; bhf[2*p+1][1] = rh[3];
                blf[2*p][0]   = rl[0]; blf[2*p+1][0] = rl[1];
                blf[2*p][1]   = rl[2]; blf[2*p+1][1] = rl[3];
            }

            #pragma unroll
            for (int mt = 0; mt < 2; mt++)
                #pragma unroll
                for (int nt = 0; nt < 8; nt++)
                    mma_bf16(acc[mt][nt], ah[mt], bhf[nt]);
            #pragma unroll
            for (int mt = 0; mt < 2; mt++)
                #pragma unroll
                for (int nt = 0; nt < 8; nt++)
                    mma_bf16(acc[mt][nt], ah[mt], blf[nt]);
            #pragma unroll
            for (int mt = 0; mt < 2; mt++)
                #pragma unroll
                for (int nt = 0; nt < 8; nt++)
                    mma_bf16(acc[mt][nt], al[mt], bhf[nt]);
        }
        __syncthreads();
        if (s + 2 < S) load_stage(s + 2);
    }

    const int row0 = bm + warp_m*32 + g;
    const int col0 = bn + warp_n*64 + tig*2;
    #pragma unroll
    for (int mt = 0; mt < 2; mt++) {
        #pragma unroll
        for (int nt = 0; nt < 8; nt++) {
            const int r = row0 + mt*16;
            const int c = col0 + nt*8;
            if (OM == 2) {
                const float scl = (c < scaleN) ? scale : 1.f;
                uint32_t h0, l0u, h1, l1u;
                split2(acc[mt][nt][0]*scl, acc[mt][nt][1]*scl, h0, l0u);
                split2(acc[mt][nt][2]*scl, acc[mt][nt][3]*scl, h1, l1u);
                *(uint32_t*)(Ch + (size_t)r * N + c)     = h0;
                *(uint32_t*)(Cl + (size_t)r * N + c)     = l0u;
                *(uint32_t*)(Ch + (size_t)(r+8) * N + c) = h1;
                *(uint32_t*)(Cl + (size_t)(r+8) * N + c) = l1u;
            } else {
                float2 v0 = make_float2(acc[mt][nt][0], acc[mt][nt][1]);
                float2 v1 = make_float2(acc[mt][nt][2], acc[mt][nt][3]);
                if (OM == 1) {
                    const float2 r0 = *(const float2*)(R + (size_t)r * N + c);
                    const float2 r1 = *(const float2*)(R + (size_t)(r+8) * N + c);
                    v0.x += r0.x; v0.y += r0.y;
                    v1.x += r1.x; v1.y += r1.y;
                }
                *(float2*)(C + (size_t)r * N + c)     = v0;
                *(float2*)(C + (size_t)(r+8) * N + c) = v1;
            }
        }
    }
}

// ======================= tensor-core causal flash attention =================
#define QKVS 6144
#define RBQ 272
#define RBV 144
#define QT_BYTES (128*RBQ)
#define KT_BYTES (64*RBQ)
#define VT_BYTES (128*RBV)
#define STAGE_B  (2*KT_BYTES + 2*VT_BYTES)
#define ATTN_SMEM (2*QT_BYTES + 2*STAGE_B)

__global__ __launch_bounds__(256) void attn_mma_k(
    const __nv_bfloat16* __restrict__ qkvh, const __nv_bfloat16* __restrict__ qkvl,
    const __nv_bfloat16* __restrict__ vh, const __nv_bfloat16* __restrict__ vl,
    __nv_bfloat16* __restrict__ Oh, __nv_bfloat16* __restrict__ Ol)
{
    extern __shared__ char sm[];
    const uint32_t sb = smem_u32(sm);

    const int tid = threadIdx.x, lane = tid & 31, wid = tid >> 5;
    const int g = lane >> 2, tig = lane & 3;
    const int qt = 15 - blockIdx.x, h = blockIdx.y, b = blockIdx.z;
    const int ntiles = 2 * (qt + 1);

    {
        const size_t gq = ((size_t)(b*2048 + qt*128) * QKVS + h*128) * 2;
        #pragma unroll
        for (int i = 0; i < 16; i++) {
            const int c = tid + i*256;
            const int t = c >> 11;
            const int cc = c & 2047;
            const int row = cc >> 4, col = cc & 15;
            const char* gp = (const char*)(t ? qkvl : qkvh) + gq + (size_t)row*(QKVS*2) + col*16;
            cp16(sb + (t ? QT_BYTES : 0) + row*RBQ + col*16, gp);
        }
        CP_COMMIT();
    }

    auto load_stage = [&](int kt) {
        const uint32_t base = sb + 2*QT_BYTES + (uint32_t)(kt & 1) * STAGE_B;
        const size_t gk = ((size_t)(b*2048 + kt*64) * QKVS + 2048 + h*128) * 2;
        const size_t gv = (((size_t)((b*16 + h)*128)) * 2048 + kt*64) * 2;
        #pragma unroll
        for (int i = 0; i < 16; i++) {
            const int c = tid + i*256;
            const int sel = c >> 10;
            const int cc = c & 1023;
            if (sel < 2) {
                const int row = cc >> 4, col = cc & 15;
                const char* gp = (const char*)(sel ? qkvl : qkvh) + gk + (size_t)row*(QKVS*2) + col*16;
                cp16(base + (sel ? KT_BYTES : 0) + row*RBQ + col*16, gp);
            } else {
                const int row = cc >> 3, col = cc & 7;
                const char* gp = (const char*)(sel == 3 ? vl : vh) + gv + (size_t)row*4096 + col*16;
                cp16(base + 2*KT_BYTES + (sel == 3 ? VT_BYTES : 0) + row*RBV + col*16, gp);
            }
        }
        CP_COMMIT();
    };

    load_stage(0);
    load_stage(1);

    float accO[16][4];
    #pragma unroll
    for (int nt = 0; nt < 16; nt++)
        #pragma unroll
        for (int e = 0; e < 4; e++) accO[nt][e] = 0.f;
    float m0 = -INFINITY, m1 = -INFINITY, l0 = 0.f, l1 = 0.f;

    const int row0 = wid * 16;
    const int qrow0 = qt*128 + row0 + g;

    for (int s = 0; s < ntiles; s++) {
        if (s + 1 < ntiles) { CP_WAIT(1); } else { CP_WAIT(0); }
        __syncthreads();
        const char* stg = sm + 2*QT_BYTES + (size_t)(s & 1) * STAGE_B;

        float accS[8][4];
        #pragma unroll
        for (int nt = 0; nt < 8; nt++)
            #pragma unroll
            for (int e = 0; e < 4; e++) accS[nt][e] = 0.f;

        #pragma unroll
        for (int ks = 0; ks < 8; ks++) {
            const int kb = ks*32 + tig*4;
            uint32_t ah[4], al[4], bh2[8][2], bl2[8][2];
            const char* ra = sm + (row0 + g)*RBQ + kb;
            ah[0] = *(const uint32_t*)(ra);
            ah[1] = *(const uint32_t*)(ra + 8*RBQ);
            ah[2] = *(const uint32_t*)(ra + 16);
            ah[3] = *(const uint32_t*)(ra + 8*RBQ + 16);
            al[0] = *(const uint32_t*)(ra + QT_BYTES);
            al[1] = *(const uint32_t*)(ra + QT_BYTES + 8*RBQ);
            al[2] = *(const uint32_t*)(ra + QT_BYTES + 16);
            al[3] = *(const uint32_t*)(ra + QT_BYTES + 8*RBQ + 16);
            #pragma unroll
            for (int nt = 0; nt < 8; nt++) {
                const char* rb = stg + (nt*8 + g)*RBQ + kb;
                bh2[nt][0] = *(const uint32_t*)(rb);
                bh2[nt][1] = *(const uint32_t*)(rb + 16);
                bl2[nt][0] = *(const uint32_t*)(rb + KT_BYTES);
                bl2[nt][1] = *(const uint32_t*)(rb + KT_BYTES + 16);
            }
            #pragma unroll
            for (int nt = 0; nt < 8; nt++) mma_bf16(accS[nt], ah, bh2[nt]);
            #pragma unroll
            for (int nt = 0; nt < 8; nt++) mma_bf16(accS[nt], ah, bl2[nt]);
            #pragma unroll
            for (int nt = 0; nt < 8; nt++) mma_bf16(accS[nt], al, bh2[nt]);
        }

        if (s >= ntiles - 2) {
            #pragma unroll
            for (int nt = 0; nt < 8; nt++) {
                const int col = s*64 + nt*8 + tig*2;
                if (col     > qrow0)     accS[nt][0] = -INFINITY;
                if (col + 1 > qrow0)     accS[nt][1] = -INFINITY;
                if (col     > qrow0 + 8) accS[nt][2] = -INFINITY;
                if (col + 1 > qrow0 + 8) accS[nt][3] = -INFINITY;
            }
        }

        float mt0 = -INFINITY, mt1 = -INFINITY;
        #pragma unroll
        for (int nt = 0; nt < 8; nt++) {
            mt0 = fmaxf(mt0, fmaxf(accS[nt][0], accS[nt][1]));
            mt1 = fmaxf(mt1, fmaxf(accS[nt][2], accS[nt][3]));
        }
        mt0 = fmaxf(mt0, __shfl_xor_sync(0xffffffffu, mt0, 1));
        mt0 = fmaxf(mt0, __shfl_xor_sync(0xffffffffu, mt0, 2));
        mt1 = fmaxf(mt1, __shfl_xor_sync(0xffffffffu, mt1, 1));
        mt1 = fmaxf(mt1, __shfl_xor_sync(0xffffffffu, mt1, 2));

        const float mn0 = fmaxf(m0, mt0), mn1 = fmaxf(m1, mt1);
        const float sc0 = __expf(m0 - mn0), sc1 = __expf(m1 - mn1);
        m0 = mn0; m1 = mn1;

        float rs0 = 0.f, rs1 = 0.f;
        #pragma unroll
        for (int nt = 0; nt < 8; nt++) {
            accS[nt][0] = __expf(accS[nt][0] - mn0);
            accS[nt][1] = __expf(accS[nt][1] - mn0);
            accS[nt][2] = __expf(accS[nt][2] - mn1);
            accS[nt][3] = __expf(accS[nt][3] - mn1);
            rs0 += accS[nt][0] + accS[nt][1];
            rs1 += accS[nt][2] + accS[nt][3];
        }
        rs0 += __shfl_xor_sync(0xffffffffu, rs0, 1);
        rs0 += __shfl_xor_sync(0xffffffffu, rs0, 2);
        rs1 += __shfl_xor_sync(0xffffffffu, rs1, 1);
        rs1 += __shfl_xor_sync(0xffffffffu, rs1, 2);
        l0 = l0*sc0 + rs0;
        l1 = l1*sc1 + rs1;

        #pragma unroll
        for (int nt = 0; nt < 16; nt++) {
            accO[nt][0] *= sc0; accO[nt][1] *= sc0;
            accO[nt][2] *= sc1; accO[nt][3] *= sc1;
        }

        #pragma unroll
        for (int kk = 0; kk < 4; kk++) {
            uint32_t ph[4], pl[4];
            split2(accS[2*kk][0],   accS[2*kk][1],   ph[0], pl[0]);
            split2(accS[2*kk][2],   accS[2*kk][3],   ph[1], pl[1]);
            split2(accS[2*kk+1][0], accS[2*kk+1][1], ph[2], pl[2]);
            split2(accS[2*kk+1][2], accS[2*kk+1][3], ph[3], pl[3]);
            const int kb = kk*32 + tig*4;
            #pragma unroll
            for (int nt = 0; nt < 16; nt++) {
                const char* rv = stg + 2*KT_BYTES + (nt*8 + g)*RBV + kb;
                uint32_t vbh[2], vbl[2];
                vbh[0] = *(const uint32_t*)(rv);
                vbh[1] = *(const uint32_t*)(rv + 16);
                vbl[0] = *(const uint32_t*)(rv + VT_BYTES);
                vbl[1] = *(const uint32_t*)(rv + VT_BYTES + 16);
                mma_bf16(accO[nt], ph, vbh);
                mma_bf16(accO[nt], ph, vbl);
                mma_bf16(accO[nt], pl, vbh);
            }
        }

        __syncthreads();
        if (s + 2 < ntiles) load_stage(s + 2);
    }

    const float inv0 = 1.f / l0, inv1 = 1.f / l1;
    const size_t ob = ((size_t)(b*2048 + qt*128 + row0 + g)) * 2048 + h*128;
    #pragma unroll
    for (int nt = 0; nt < 16; nt++) {
        const int c = nt*8 + tig*2;
        uint32_t h0, l0u, h1, l1u;
        split2(accO[nt][0]*inv0, accO[nt][1]*inv0, h0, l0u);
        split2(accO[nt][2]*inv1, accO[nt][3]*inv1, h1, l1u);
        *(uint32_t*)(Oh + ob + c)           = h0;
        *(uint32_t*)(Ol + ob + c)           = l0u;
        *(uint32_t*)(Oh + ob + 8*2048 + c)  = h1;
        *(uint32_t*)(Ol + ob + 8*2048 + c)  = l1u;
    }
}

// ======================= weight transpose + split ==========================
__global__ void transconv_k(const float* __restrict__ W,
                            __nv_bfloat16* __restrict__ Thi, __nv_bfloat16* __restrict__ Tlo,
                            int K, int N)
{
    __shared__ float t[32][33];
    const int n0 = blockIdx.x * 32, k0 = blockIdx.y * 32;
    const int tx = threadIdx.x, ty = threadIdx.y;
    #pragma unroll
    for (int i = ty; i < 32; i += 8)
        t[i][tx] = W[(size_t)(k0 + i) * N + n0 + tx];
    __syncthreads();
    #pragma unroll
    for (int i = ty; i < 32; i += 8) {
        const float v = t[tx][i];
        const __nv_bfloat16 hi = __float2bfloat16(v);
        const __nv_bfloat16 lo = __float2bfloat16(v - __bfloat162float(hi));
        const size_t o = (size_t)(n0 + i) * K + k0 + tx;
        Thi[o] = hi; Tlo[o] = lo;
    }
}

// ======================= V transpose (bf16 hi/lo pair) ======================
__global__ void vtrans_bf_k(const __nv_bfloat16* __restrict__ Vh,
                            const __nv_bfloat16* __restrict__ Vl,
                            __nv_bfloat16* __restrict__ Th, __nv_bfloat16* __restrict__ Tl)
{
    __shared__ __nv_bfloat16 th[32][33], tl[32][33];
    const int kv0 = blockIdx.x * 32, hd0 = blockIdx.y * 32, bh = blockIdx.z;
    const int b = bh >> 4, h = bh & 15;
    const int tx = threadIdx.x, ty = threadIdx.y;
    #pragma unroll
    for (int i = ty; i < 32; i += 8) {
        const size_t src = (size_t)(b*2048 + kv0 + i) * QKVS + 4096 + h*128 + hd0 + tx;
        th[i][tx] = Vh[src];
        tl[i][tx] = Vl[src];
    }
    __syncthreads();
    #pragma unroll
    for (int i = ty; i < 32; i += 8) {
        const size_t o = ((size_t)(bh*128 + hd0 + i)) * 2048 + kv0 + tx;
        Th[o] = th[tx][i];
        Tl[o] = tl[tx][i];
    }
}

// ======================= RMSNorm -> bf16 hi/lo ==============================
__global__ __launch_bounds__(256) void rmsnorm_conv_k(
    const float* __restrict__ x, const float* __restrict__ w,
    __nv_bfloat16* __restrict__ yh, __nv_bfloat16* __restrict__ yl)
{
    const int row = blockIdx.x;
    const float4* xr = (const float4*)(x + (size_t)row * HID);
    const float4* w4 = (const float4*)w;

    float4 v0 = xr[threadIdx.x];
    float4 v1 = xr[threadIdx.x + 256];
    float ss = v0.x*v0.x + v0.y*v0.y + v0.z*v0.z + v0.w*v0.w
             + v1.x*v1.x + v1.y*v1.y + v1.z*v1.z + v1.w*v1.w;
    #pragma unroll
    for (int off = 16; off > 0; off >>= 1) ss += __shfl_xor_sync(0xffffffffu, ss, off);

    __shared__ float red[8]; __shared__ float s_inv;
    if ((threadIdx.x & 31) == 0) red[threadIdx.x >> 5] = ss;
    __syncthreads();
    if (threadIdx.x == 0) {
        float t = 0.f;
        #pragma unroll
        for (int i = 0; i < 8; i++) t += red[i];
        s_inv = rsqrtf(t * (1.f / (float)HID) + 1e-6f);
    }
    __syncthreads();
    const float inv = s_inv;

    const float4 w0 = w4[threadIdx.x], w1 = w4[threadIdx.x + 256];
    float o[8] = { v0.x*inv*w0.x, v0.y*inv*w0.y, v0.z*inv*w0.z, v0.w*inv*w0.w,
                   v1.x*inv*w1.x, v1.y*inv*w1.y, v1.z*inv*w1.z, v1.w*inv*w1.w };
    const size_t b0 = (size_t)row * HID + threadIdx.x * 4;
    const size_t b1 = (size_t)row * HID + (threadIdx.x + 256) * 4;
    #pragma unroll
    for (int j = 0; j < 4; j++) {
        __nv_bfloat16 h = __float2bfloat16(o[j]);
        yh[b0 + j] = h; yl[b0 + j] = __float2bfloat16(o[j] - __bfloat162float(h));
    }
    #pragma unroll
    for (int j = 0; j < 4; j++) {
        __nv_bfloat16 h = __float2bfloat16(o[4 + j]);
        yh[b1 + j] = h; yl[b1 + j] = __float2bfloat16(o[4 + j] - __bfloat162float(h));
    }
}

// ======================= silu(g)*u on fused gu buffer -> bf16 hi/lo =========
__global__ void silu_conv2_k(const float* __restrict__ gu,
                             __nv_bfloat16* __restrict__ mh, __nv_bfloat16* __restrict__ ml)
{
    const int i = blockIdx.x * 256 + threadIdx.x;
    const int row = i >> 11;
    const int j4 = i & 2047;
    const float4 gv = ((const float4*)gu)[(size_t)row*4096 + j4];
    const float4 uv = ((const float4*)gu)[(size_t)row*4096 + 2048 + j4];
    float r[4];
    r[0] = gv.x / (1.f + __expf(-gv.x)) * uv.x;
    r[1] = gv.y / (1.f + __expf(-gv.y)) * uv.y;
    r[2] = gv.z / (1.f + __expf(-gv.z)) * uv.z;
    r[3] = gv.w / (1.f + __expf(-gv.w)) * uv.w;
    const size_t b = (size_t)row * INTER + j4 * 4;
    #pragma unroll
    for (int j = 0; j < 4; j++) {
        __nv_bfloat16 h = __float2bfloat16(r[j]);
        mh[b + j] = h; ml[b + j] = __float2bfloat16(r[j] - __bfloat162float(h));
    }
}

// ======================= launch =============================================
extern "C" void kernel_launch(void* const* d_in, const int* in_sizes, int n_in,
                              void* d_out, int out_size)
{
    const float* hidden = (const float*)d_in[0];
    const float* wq  = (const float*)d_in[1];
    const float* wk  = (const float*)d_in[2];
    const float* wv  = (const float*)d_in[3];
    const float* wo  = (const float*)d_in[4];
    const float* wg  = (const float*)d_in[5];
    const float* wu  = (const float*)d_in[6];
    const float* wd  = (const float*)d_in[7];
    const float* ln1 = (const float*)d_in[8];
    const float* ln2 = (const float*)d_in[9];

    __nv_bfloat16 *pwqkv_h,*pwqkv_l,*pwo_h,*pwo_l,*pwgu_h,*pwgu_l,*pwd_h,*pwd_l;
    __nv_bfloat16 *px_h,*px_l,*pat_h,*pat_l,*pm_h,*pm_l;
    __nv_bfloat16 *pqkv_h,*pqkv_l,*pvt_h,*pvt_l;
    float *h1,*gu;
    cudaGetSymbolAddress((void**)&pwqkv_h, w_qkv_hi); cudaGetSymbolAddress((void**)&pwqkv_l, w_qkv_lo);
    cudaGetSymbolAddress((void**)&pwo_h,   w_o_hi);   cudaGetSymbolAddress((void**)&pwo_l,   w_o_lo);
    cudaGetSymbolAddress((void**)&pwgu_h,  w_gu_hi);  cudaGetSymbolAddress((void**)&pwgu_l,  w_gu_lo);
    cudaGetSymbolAddress((void**)&pwd_h,   w_d_hi);   cudaGetSymbolAddress((void**)&pwd_l,   w_d_lo);
    cudaGetSymbolAddress((void**)&px_h,  a_x_hi);  cudaGetSymbolAddress((void**)&px_l,  a_x_lo);
    cudaGetSymbolAddress((void**)&pat_h, a_at_hi); cudaGetSymbolAddress((void**)&pat_l, a_at_lo);
    cudaGetSymbolAddress((void**)&pm_h,  a_m_hi);  cudaGetSymbolAddress((void**)&pm_l,  a_m_lo);
    cudaGetSymbolAddress((void**)&pqkv_h, qkv_hi); cudaGetSymbolAddress((void**)&pqkv_l, qkv_lo);
    cudaGetSymbolAddress((void**)&pvt_h, vt_hi);   cudaGetSymbolAddress((void**)&pvt_l, vt_lo);
    cudaGetSymbolAddress((void**)&h1, s_h1);       cudaGetSymbolAddress((void**)&gu, s_gu);

    cudaFuncSetAttribute(gemm3bf<0>, cudaFuncAttributeMaxDynamicSharedMemorySize, GEMM_SMEM);
    cudaFuncSetAttribute(gemm3bf<1>, cudaFuncAttributeMaxDynamicSharedMemorySize, GEMM_SMEM);
    cudaFuncSetAttribute(gemm3bf<2>, cudaFuncAttributeMaxDynamicSharedMemorySize, GEMM_SMEM);
    cudaFuncSetAttribute(attn_mma_k, cudaFuncAttributeMaxDynamicSharedMemorySize, ATTN_SMEM);

    // weight transpose+split into fused buffers
    dim3 tb(32, 8);
    transconv_k<<<dim3(HID/32,  HID/32),  tb>>>(wq, pwqkv_h,                 pwqkv_l,                 HID, HID);
    transconv_k<<<dim3(HID/32,  HID/32),  tb>>>(wk, pwqkv_h + (size_t)HID*HID,   pwqkv_l + (size_t)HID*HID,   HID, HID);
    transconv_k<<<dim3(HID/32,  HID/32),  tb>>>(wv, pwqkv_h + (size_t)2*HID*HID, pwqkv_l + (size_t)2*HID*HID, HID, HID);
    transconv_k<<<dim3(HID/32,  HID/32),  tb>>>(wo, pwo_h, pwo_l, HID, HID);
    transconv_k<<<dim3(INTER/32,HID/32),  tb>>>(wg, pwgu_h,                    pwgu_l,                    HID, INTER);
    transconv_k<<<dim3(INTER/32,HID/32),  tb>>>(wu, pwgu_h + (size_t)INTER*HID, pwgu_l + (size_t)INTER*HID, HID, INTER);
    transconv_k<<<dim3(HID/32,  INTER/32),tb>>>(wd, pwd_h, pwd_l, INTER, HID);

    // 1) rmsnorm -> bf16 hi/lo
    rmsnorm_conv_k<<<MTOK, 256>>>(hidden, ln1, px_h, px_l);

    // 2) fused QKV projection (Q cols scaled by 1/sqrt(d)), bf16 hi/lo out
    const float sc = 0.08838834764831845f;
    gemm3bf<2><<<dim3(3*HID/128, MTOK/128), 256, GEMM_SMEM>>>(
        px_h, px_l, pwqkv_h, pwqkv_l, nullptr, nullptr,
        pqkv_h, pqkv_l, sc, HID, MTOK, 3*HID, HID);

    // V transpose (hi/lo bf16)
    vtrans_bf_k<<<dim3(64, 4, 32), tb>>>(pqkv_h, pqkv_l, pvt_h, pvt_l);

    // 3) tensor-core attention -> bf16 hi/lo
    attn_mma_k<<<dim3(16, 16, 2), 256, ATTN_SMEM>>>(pqkv_h, pqkv_l, pvt_h, pvt_l,
                                                    pat_h, pat_l);

    // 4) O-proj + residual
    gemm3bf<1><<<dim3(HID/128, MTOK/128), 256, GEMM_SMEM>>>(
        pat_h, pat_l, pwo_h, pwo_l, hidden, h1,
        nullptr, nullptr, 1.f, 0, MTOK, HID, HID);

    // 5) rmsnorm2 -> bf16 hi/lo
    rmsnorm_conv_k<<<MTOK, 256>>>(h1, ln2, px_h, px_l);

    // 6) fused gate+up GEMM (N=16384), fp32 out
    gemm3bf<0><<<dim3(2*INTER/128, MTOK/128), 256, GEMM_SMEM>>>(
        px_h, px_l, pwgu_h, pwgu_l, nullptr, gu,
        nullptr, nullptr, 1.f, 0, MTOK, 2*INTER, HID);

    // silu(g)*u -> bf16 hi/lo
    silu_conv2_k<<<(MTOK*INTER/4 + 255)/256, 256>>>(gu, pm_h, pm_l);

    // down-proj + residual -> d_out
    gemm3bf<1><<<dim3(HID/128, MTOK/128), 256, GEMM_SMEM>>>(
        pm_h, pm_l, pwd_h, pwd_l, h1, (float*)d_out,
        nullptr, nullptr, 1.f, 0, MTOK, HID, INTER);
}

// round 7
// speedup vs baseline: 1.0758x; 1.0758x over previous
#include <cuda_runtime.h>
#include <cuda_bf16.h>
#include <math.h>
#include <stdint.h>

#define MTOK 4096      // B*S
#define HID  2048
#define INTER 8192

// ======================= device scratch (no allocations) ====================
__device__ __nv_bfloat16 w_qkv_hi[(size_t)3*HID*HID], w_qkv_lo[(size_t)3*HID*HID];
__device__ __nv_bfloat16 w_o_hi[HID*HID],  w_o_lo[HID*HID];
__device__ __nv_bfloat16 w_gu_hi[(size_t)2*INTER*HID], w_gu_lo[(size_t)2*INTER*HID];
__device__ __nv_bfloat16 w_d_hi[(size_t)HID*INTER], w_d_lo[(size_t)HID*INTER];
__device__ __nv_bfloat16 a_x_hi[MTOK*HID],  a_x_lo[MTOK*HID];
__device__ __nv_bfloat16 a_at_hi[MTOK*HID], a_at_lo[MTOK*HID];
__device__ __nv_bfloat16 a_m_hi[(size_t)MTOK*INTER], a_m_lo[(size_t)MTOK*INTER];
__device__ __nv_bfloat16 qkv_hi[(size_t)MTOK*3*HID], qkv_lo[(size_t)MTOK*3*HID];
__device__ __nv_bfloat16 vt_hi[MTOK*HID], vt_lo[MTOK*HID];   // [b*16+h][hd][kv]
__device__ float s_h1[MTOK*HID];
__device__ float s_gu[(size_t)MTOK*2*INTER];

// ======================= helpers ============================================
__device__ __forceinline__ uint32_t smem_u32(const void* p) {
    uint32_t a;
    asm("{ .reg .u64 t; cvta.to.shared.u64 t, %1; cvt.u32.u64 %0, t; }" : "=r"(a) : "l"(p));
    return a;
}
__device__ __forceinline__ void cp16(uint32_t s, const void* g) {
    asm volatile("cp.async.cg.shared.global [%0], [%1], 16;" :: "r"(s), "l"(g));
}
#define CP_COMMIT() asm volatile("cp.async.commit_group;")
#define CP_WAIT(N)  asm volatile("cp.async.wait_group %0;" :: "n"(N))

__device__ __forceinline__ void mma_bf16(float* c, const uint32_t* a, const uint32_t* b) {
    asm volatile(
        "mma.sync.aligned.m16n8k16.row.col.f32.bf16.bf16.f32 "
        "{%0,%1,%2,%3}, {%4,%5,%6,%7}, {%8,%9}, {%0,%1,%2,%3};"
        : "+f"(c[0]), "+f"(c[1]), "+f"(c[2]), "+f"(c[3])
        : "r"(a[0]), "r"(a[1]), "r"(a[2]), "r"(a[3]), "r"(b[0]), "r"(b[1]));
}
__device__ __forceinline__ void split2(float x, float y, uint32_t& hi, uint32_t& lo) {
    __nv_bfloat162 h;
    h.x = __float2bfloat16(x); h.y = __float2bfloat16(y);
    __nv_bfloat162 l;
    l.x = __float2bfloat16(x - __bfloat162float(h.x));
    l.y = __float2bfloat16(y - __bfloat162float(h.y));
    hi = *reinterpret_cast<uint32_t*>(&h);
    lo = *reinterpret_cast<uint32_t*>(&l);
}

// ======================= bf16x3 mma.sync GEMM ===============================
// OM: 0 = fp32 out, 1 = fp32 out + residual, 2 = bf16 hi/lo out (scale cols<scaleN)
// BM=BN=128, BK=64, 256 threads (8 warps: 4 M x 2 N).
// 3-stage cp.async ring buffer, ONE __syncthreads per stage.
#define RB   144
#define TILE (128*RB)            // 18432
#define STG  (4*TILE)            // 73728: Ah, Al, Bh, Bl
#define GEMM_SMEM (3*STG)        // 221184

template<int OM>
__global__ __launch_bounds__(256) void gemm3bf(
    const __nv_bfloat16* __restrict__ Ahi, const __nv_bfloat16* __restrict__ Alo,
    const __nv_bfloat16* __restrict__ Bhi, const __nv_bfloat16* __restrict__ Blo,
    const float* __restrict__ R, float* __restrict__ C,
    __nv_bfloat16* __restrict__ Ch, __nv_bfloat16* __restrict__ Cl,
    float scale, int scaleN, int M, int N, int K)
{
    extern __shared__ char sm[];
    const uint32_t sbase = smem_u32(sm);

    const int tid = threadIdx.x;
    const int lane = tid & 31;
    const int wid = tid >> 5;
    const int g = lane >> 2, tig = lane & 3;
    const int warp_m = wid & 3;
    const int warp_n = wid >> 2;
    const int bm = blockIdx.y * 128;
    const int bn = blockIdx.x * 128;

    const int crow = tid >> 3;            // 0..31
    const int ccolB = (tid & 7) * 16;

    const int S = K >> 6;

    auto load_stage = [&](int s) {
        const uint32_t b = sbase + (uint32_t)(s % 3) * STG;
        const int k0 = s << 6;
        const size_t ga = ((size_t)(bm + crow) * K + k0) * 2 + ccolB;
        const size_t gb = ((size_t)(bn + crow) * K + k0) * 2 + ccolB;
        const size_t rstep = (size_t)32 * K * 2;
        const char* pah = (const char*)Ahi + ga;
        const char* pal = (const char*)Alo + ga;
        const char* pbh = (const char*)Bhi + gb;
        const char* pbl = (const char*)Blo + gb;
        #pragma unroll
        for (int i = 0; i < 4; i++) {
            const uint32_t so = (uint32_t)((crow + 32*i) * RB + ccolB);
            cp16(b + so,            pah); pah += rstep;
            cp16(b + TILE   + so,   pal); pal += rstep;
            cp16(b + 2*TILE + so,   pbh); pbh += rstep;
            cp16(b + 3*TILE + so,   pbl); pbl += rstep;
        }
        CP_COMMIT();
    };

    load_stage(0);
    if (S > 1) load_stage(1);

    float acc[2][8][4];
    #pragma unroll
    for (int mt = 0; mt < 2; mt++)
        #pragma unroll
        for (int nt = 0; nt < 8; nt++)
            #pragma unroll
            for (int e = 0; e < 4; e++) acc[mt][nt][e] = 0.f;

    const int arow0 = warp_m * 32 + g;
    const int brow0 = warp_n * 64 + g;

    for (int s = 0; s < S; ++s) {
        if (s + 1 < S) { CP_WAIT(1); } else { CP_WAIT(0); }
        __syncthreads();
        // buffer (s+2)%3 == (s-1)%3 is free: all warps finished compute(s-1)
        if (s + 2 < S) load_stage(s + 2);

        const char* b = sm + (size_t)(s % 3) * STG;

        #pragma unroll
        for (int ks = 0; ks < 4; ++ks) {
            const int kb = ks * 32 + tig * 4;

            uint32_t ah[2][4], al[2][4], bhf[8][2], blf[8][2];
            #pragma unroll
            for (int mt = 0; mt < 2; mt++) {
                const char* ra = b + (arow0 + mt*16) * RB + kb;
                ah[mt][0] = *(const uint32_t*)(ra);
                ah[mt][1] = *(const uint32_t*)(ra + 8*RB);
                ah[mt][2] = *(const uint32_t*)(ra + 16);
                ah[mt][3] = *(const uint32_t*)(ra + 8*RB + 16);
                const char* rl = ra + TILE;
                al[mt][0] = *(const uint32_t*)(rl);
                al[mt][1] = *(const uint32_t*)(rl + 8*RB);
                al[mt][2] = *(const uint32_t*)(rl + 16);
                al[mt][3] = *(const uint32_t*)(rl + 8*RB + 16);
            }
            #pragma unroll
            for (int nt = 0; nt < 8; nt++) {
                const char* rb = b + 2*TILE + (brow0 + nt*8) * RB + kb;
                bhf[nt][0] = *(const uint32_t*)(rb);
                bhf[nt][1] = *(const uint32_t*)(rb + 16);
                blf[nt][0] = *(const uint32_t*)(rb + TILE);
                blf[nt][1] = *(const uint32_t*)(rb + TILE + 16);
            }

            #pragma unroll
            for (int mt = 0; mt < 2; mt++)
                #pragma unroll
                for (int nt = 0; nt < 8; nt++)
                    mma_bf16(acc[mt][nt], ah[mt], bhf[nt]);
            #pragma unroll
            for (int mt = 0; mt < 2; mt++)
                #pragma unroll
                for (int nt = 0; nt < 8; nt++)
                    mma_bf16(acc[mt][nt], ah[mt], blf[nt]);
            #pragma unroll
            for (int mt = 0; mt < 2; mt++)
                #pragma unroll
                for (int nt = 0; nt < 8; nt++)
                    mma_bf16(acc[mt][nt], al[mt], bhf[nt]);
        }
    }

    const int row0 = bm + warp_m*32 + g;
    const int col0 = bn + warp_n*64 + tig*2;
    #pragma unroll
    for (int mt = 0; mt < 2; mt++) {
        #pragma unroll
        for (int nt = 0; nt < 8; nt++) {
            const int r = row0 + mt*16;
            const int c = col0 + nt*8;
            if (OM == 2) {
                const float scl = (c < scaleN) ? scale : 1.f;
                uint32_t h0, l0u, h1, l1u;
                split2(acc[mt][nt][0]*scl, acc[mt][nt][1]*scl, h0, l0u);
                split2(acc[mt][nt][2]*scl, acc[mt][nt][3]*scl, h1, l1u);
                *(uint32_t*)(Ch + (size_t)r * N + c)     = h0;
                *(uint32_t*)(Cl + (size_t)r * N + c)     = l0u;
                *(uint32_t*)(Ch + (size_t)(r+8) * N + c) = h1;
                *(uint32_t*)(Cl + (size_t)(r+8) * N + c) = l1u;
            } else {
                float2 v0 = make_float2(acc[mt][nt][0], acc[mt][nt][1]);
                float2 v1 = make_float2(acc[mt][nt][2], acc[mt][nt][3]);
                if (OM == 1) {
                    const float2 r0 = *(const float2*)(R + (size_t)r * N + c);
                    const float2 r1 = *(const float2*)(R + (size_t)(r+8) * N + c);
                    v0.x += r0.x; v0.y += r0.y;
                    v1.x += r1.x; v1.y += r1.y;
                }
                *(float2*)(C + (size_t)r * N + c)     = v0;
                *(float2*)(C + (size_t)(r+8) * N + c) = v1;
            }
        }
    }
}

// ======================= tensor-core causal flash attention =================
#define QKVS 6144
#define RBQ 272
#define RBV 144
#define QT_BYTES (128*RBQ)
#define KT_BYTES (64*RBQ)
#define VT_BYTES (128*RBV)
#define STAGE_B  (2*KT_BYTES + 2*VT_BYTES)
#define ATTN_SMEM (2*QT_BYTES + 2*STAGE_B)

__global__ __launch_bounds__(256) void attn_mma_k(
    const __nv_bfloat16* __restrict__ qkvh, const __nv_bfloat16* __restrict__ qkvl,
    const __nv_bfloat16* __restrict__ vh, const __nv_bfloat16* __restrict__ vl,
    __nv_bfloat16* __restrict__ Oh, __nv_bfloat16* __restrict__ Ol)
{
    extern __shared__ char sm[];
    const uint32_t sb = smem_u32(sm);

    const int tid = threadIdx.x, lane = tid & 31, wid = tid >> 5;
    const int g = lane >> 2, tig = lane & 3;
    const int qt = 15 - blockIdx.x, h = blockIdx.y, b = blockIdx.z;
    const int ntiles = 2 * (qt + 1);

    {
        const size_t gq = ((size_t)(b*2048 + qt*128) * QKVS + h*128) * 2;
        #pragma unroll
        for (int i = 0; i < 16; i++) {
            const int c = tid + i*256;
            const int t = c >> 11;
            const int cc = c & 2047;
            const int row = cc >> 4, col = cc & 15;
            const char* gp = (const char*)(t ? qkvl : qkvh) + gq + (size_t)row*(QKVS*2) + col*16;
            cp16(sb + (t ? QT_BYTES : 0) + row*RBQ + col*16, gp);
        }
        CP_COMMIT();
    }

    auto load_stage = [&](int kt) {
        const uint32_t base = sb + 2*QT_BYTES + (uint32_t)(kt & 1) * STAGE_B;
        const size_t gk = ((size_t)(b*2048 + kt*64) * QKVS + 2048 + h*128) * 2;
        const size_t gv = (((size_t)((b*16 + h)*128)) * 2048 + kt*64) * 2;
        #pragma unroll
        for (int i = 0; i < 16; i++) {
            const int c = tid + i*256;
            const int sel = c >> 10;
            const int cc = c & 1023;
            if (sel < 2) {
                const int row = cc >> 4, col = cc & 15;
                const char* gp = (const char*)(sel ? qkvl : qkvh) + gk + (size_t)row*(QKVS*2) + col*16;
                cp16(base + (sel ? KT_BYTES : 0) + row*RBQ + col*16, gp);
            } else {
                const int row = cc >> 3, col = cc & 7;
                const char* gp = (const char*)(sel == 3 ? vl : vh) + gv + (size_t)row*4096 + col*16;
                cp16(base + 2*KT_BYTES + (sel == 3 ? VT_BYTES : 0) + row*RBV + col*16, gp);
            }
        }
        CP_COMMIT();
    };

    load_stage(0);
    load_stage(1);

    float accO[16][4];
    #pragma unroll
    for (int nt = 0; nt < 16; nt++)
        #pragma unroll
        for (int e = 0; e < 4; e++) accO[nt][e] = 0.f;
    float m0 = -INFINITY, m1 = -INFINITY, l0 = 0.f, l1 = 0.f;

    const int row0 = wid * 16;
    const int qrow0 = qt*128 + row0 + g;

    for (int s = 0; s < ntiles; s++) {
        if (s + 1 < ntiles) { CP_WAIT(1); } else { CP_WAIT(0); }
        __syncthreads();
        const char* stg = sm + 2*QT_BYTES + (size_t)(s & 1) * STAGE_B;

        float accS[8][4];
        #pragma unroll
        for (int nt = 0; nt < 8; nt++)
            #pragma unroll
            for (int e = 0; e < 4; e++) accS[nt][e] = 0.f;

        #pragma unroll
        for (int ks = 0; ks < 8; ks++) {
            const int kb = ks*32 + tig*4;
            uint32_t ah[4], al[4], bh2[8][2], bl2[8][2];
            const char* ra = sm + (row0 + g)*RBQ + kb;
            ah[0] = *(const uint32_t*)(ra);
            ah[1] = *(const uint32_t*)(ra + 8*RBQ);
            ah[2] = *(const uint32_t*)(ra + 16);
            ah[3] = *(const uint32_t*)(ra + 8*RBQ + 16);
            al[0] = *(const uint32_t*)(ra + QT_BYTES);
            al[1] = *(const uint32_t*)(ra + QT_BYTES + 8*RBQ);
            al[2] = *(const uint32_t*)(ra + QT_BYTES + 16);
            al[3] = *(const uint32_t*)(ra + QT_BYTES + 8*RBQ + 16);
            #pragma unroll
            for (int nt = 0; nt < 8; nt++) {
                const char* rb = stg + (nt*8 + g)*RBQ + kb;
                bh2[nt][0] = *(const uint32_t*)(rb);
                bh2[nt][1] = *(const uint32_t*)(rb + 16);
                bl2[nt][0] = *(const uint32_t*)(rb + KT_BYTES);
                bl2[nt][1] = *(const uint32_t*)(rb + KT_BYTES + 16);
            }
            #pragma unroll
            for (int nt = 0; nt < 8; nt++) mma_bf16(accS[nt], ah, bh2[nt]);
            #pragma unroll
            for (int nt = 0; nt < 8; nt++) mma_bf16(accS[nt], ah, bl2[nt]);
            #pragma unroll
            for (int nt = 0; nt < 8; nt++) mma_bf16(accS[nt], al, bh2[nt]);
        }

        if (s >= ntiles - 2) {
            #pragma unroll
            for (int nt = 0; nt < 8; nt++) {
                const int col = s*64 + nt*8 + tig*2;
                if (col     > qrow0)     accS[nt][0] = -INFINITY;
                if (col + 1 > qrow0)     accS[nt][1] = -INFINITY;
                if (col     > qrow0 + 8) accS[nt][2] = -INFINITY;
                if (col + 1 > qrow0 + 8) accS[nt][3] = -INFINITY;
            }
        }

        float mt0 = -INFINITY, mt1 = -INFINITY;
        #pragma unroll
        for (int nt = 0; nt < 8; nt++) {
            mt0 = fmaxf(mt0, fmaxf(accS[nt][0], accS[nt][1]));
            mt1 = fmaxf(mt1, fmaxf(accS[nt][2], accS[nt][3]));
        }
        mt0 = fmaxf(mt0, __shfl_xor_sync(0xffffffffu, mt0, 1));
        mt0 = fmaxf(mt0, __shfl_xor_sync(0xffffffffu, mt0, 2));
        mt1 = fmaxf(mt1, __shfl_xor_sync(0xffffffffu, mt1, 1));
        mt1 = fmaxf(mt1, __shfl_xor_sync(0xffffffffu, mt1, 2));

        const float mn0 = fmaxf(m0, mt0), mn1 = fmaxf(m1, mt1);
        const float sc0 = __expf(m0 - mn0), sc1 = __expf(m1 - mn1);
        m0 = mn0; m1 = mn1;

        float rs0 = 0.f, rs1 = 0.f;
        #pragma unroll
        for (int nt = 0; nt < 8; nt++) {
            accS[nt][0] = __expf(accS[nt][0] - mn0);
            accS[nt][1] = __expf(accS[nt][1] - mn0);
            accS[nt][2] = __expf(accS[nt][2] - mn1);
            accS[nt][3] = __expf(accS[nt][3] - mn1);
            rs0 += accS[nt][0] + accS[nt][1];
            rs1 += accS[nt][2] + accS[nt][3];
        }
        rs0 += __shfl_xor_sync(0xffffffffu, rs0, 1);
        rs0 += __shfl_xor_sync(0xffffffffu, rs0, 2);
        rs1 += __shfl_xor_sync(0xffffffffu, rs1, 1);
        rs1 += __shfl_xor_sync(0xffffffffu, rs1, 2);
        l0 = l0*sc0 + rs0;
        l1 = l1*sc1 + rs1;

        #pragma unroll
        for (int nt = 0; nt < 16; nt++) {
            accO[nt][0] *= sc0; accO[nt][1] *= sc0;
            accO[nt][2] *= sc1; accO[nt][3] *= sc1;
        }

        #pragma unroll
        for (int kk = 0; kk < 4; kk++) {
            uint32_t ph[4], pl[4];
            split2(accS[2*kk][0],   accS[2*kk][1],   ph[0], pl[0]);
            split2(accS[2*kk][2],   accS[2*kk][3],   ph[1], pl[1]);
            split2(accS[2*kk+1][0], accS[2*kk+1][1], ph[2], pl[2]);
            split2(accS[2*kk+1][2], accS[2*kk+1][3], ph[3], pl[3]);
            const int kb = kk*32 + tig*4;
            #pragma unroll
            for (int nt = 0; nt < 16; nt++) {
                const char* rv = stg + 2*KT_BYTES + (nt*8 + g)*RBV + kb;
                uint32_t vbh[2], vbl[2];
                vbh[0] = *(const uint32_t*)(rv);
                vbh[1] = *(const uint32_t*)(rv + 16);
                vbl[0] = *(const uint32_t*)(rv + VT_BYTES);
                vbl[1] = *(const uint32_t*)(rv + VT_BYTES + 16);
                mma_bf16(accO[nt], ph, vbh);
                mma_bf16(accO[nt], ph, vbl);
                mma_bf16(accO[nt], pl, vbh);
            }
        }

        __syncthreads();
        if (s + 2 < ntiles) load_stage(s + 2);
    }

    const float inv0 = 1.f / l0, inv1 = 1.f / l1;
    const size_t ob = ((size_t)(b*2048 + qt*128 + row0 + g)) * 2048 + h*128;
    #pragma unroll
    for (int nt = 0; nt < 16; nt++) {
        const int c = nt*8 + tig*2;
        uint32_t h0, l0u, h1, l1u;
        split2(accO[nt][0]*inv0, accO[nt][1]*inv0, h0, l0u);
        split2(accO[nt][2]*inv1, accO[nt][3]*inv1, h1, l1u);
        *(uint32_t*)(Oh + ob + c)           = h0;
        *(uint32_t*)(Ol + ob + c)           = l0u;
        *(uint32_t*)(Oh + ob + 8*2048 + c)  = h1;
        *(uint32_t*)(Ol + ob + 8*2048 + c)  = l1u;
    }
}

// ======================= weight transpose + split ==========================
__global__ void transconv_k(const float* __restrict__ W,
                            __nv_bfloat16* __restrict__ Thi, __nv_bfloat16* __restrict__ Tlo,
                            int K, int N)
{
    __shared__ float t[32][33];
    const int n0 = blockIdx.x * 32, k0 = blockIdx.y * 32;
    const int tx = threadIdx.x, ty = threadIdx.y;
    #pragma unroll
    for (int i = ty; i < 32; i += 8)
        t[i][tx] = W[(size_t)(k0 + i) * N + n0 + tx];
    __syncthreads();
    #pragma unroll
    for (int i = ty; i < 32; i += 8) {
        const float v = t[tx][i];
        const __nv_bfloat16 hi = __float2bfloat16(v);
        const __nv_bfloat16 lo = __float2bfloat16(v - __bfloat162float(hi));
        const size_t o = (size_t)(n0 + i) * K + k0 + tx;
        Thi[o] = hi; Tlo[o] = lo;
    }
}

// ======================= V transpose (bf16 hi/lo pair) ======================
__global__ void vtrans_bf_k(const __nv_bfloat16* __restrict__ Vh,
                            const __nv_bfloat16* __restrict__ Vl,
                            __nv_bfloat16* __restrict__ Th, __nv_bfloat16* __restrict__ Tl)
{
    __shared__ __nv_bfloat16 th[32][33], tl[32][33];
    const int kv0 = blockIdx.x * 32, hd0 = blockIdx.y * 32, bh = blockIdx.z;
    const int b = bh >> 4, h = bh & 15;
    const int tx = threadIdx.x, ty = threadIdx.y;
    #pragma unroll
    for (int i = ty; i < 32; i += 8) {
        const size_t src = (size_t)(b*2048 + kv0 + i) * QKVS + 4096 + h*128 + hd0 + tx;
        th[i][tx] = Vh[src];
        tl[i][tx] = Vl[src];
    }
    __syncthreads();
    #pragma unroll
    for (int i = ty; i < 32; i += 8) {
        const size_t o = ((size_t)(bh*128 + hd0 + i)) * 2048 + kv0 + tx;
        Th[o] = th[tx][i];
        Tl[o] = tl[tx][i];
    }
}

// ======================= RMSNorm -> bf16 hi/lo ==============================
__global__ __launch_bounds__(256) void rmsnorm_conv_k(
    const float* __restrict__ x, const float* __restrict__ w,
    __nv_bfloat16* __restrict__ yh, __nv_bfloat16* __restrict__ yl)
{
    const int row = blockIdx.x;
    const float4* xr = (const float4*)(x + (size_t)row * HID);
    const float4* w4 = (const float4*)w;

    float4 v0 = xr[threadIdx.x];
    float4 v1 = xr[threadIdx.x + 256];
    float ss = v0.x*v0.x + v0.y*v0.y + v0.z*v0.z + v0.w*v0.w
             + v1.x*v1.x + v1.y*v1.y + v1.z*v1.z + v1.w*v1.w;
    #pragma unroll
    for (int off = 16; off > 0; off >>= 1) ss += __shfl_xor_sync(0xffffffffu, ss, off);

    __shared__ float red[8]; __shared__ float s_inv;
    if ((threadIdx.x & 31) == 0) red[threadIdx.x >> 5] = ss;
    __syncthreads();
    if (threadIdx.x == 0) {
        float t = 0.f;
        #pragma unroll
        for (int i = 0; i < 8; i++) t += red[i];
        s_inv = rsqrtf(t * (1.f / (float)HID) + 1e-6f);
    }
    __syncthreads();
    const float inv = s_inv;

    const float4 w0 = w4[threadIdx.x], w1 = w4[threadIdx.x + 256];
    float o[8] = { v0.x*inv*w0.x, v0.y*inv*w0.y, v0.z*inv*w0.z, v0.w*inv*w0.w,
                   v1.x*inv*w1.x, v1.y*inv*w1.y, v1.z*inv*w1.z, v1.w*inv*w1.w };
    const size_t b0 = (size_t)row * HID + threadIdx.x * 4;
    const size_t b1 = (size_t)row * HID + (threadIdx.x + 256) * 4;
    #pragma unroll
    for (int j = 0; j < 4; j++) {
        __nv_bfloat16 h = __float2bfloat16(o[j]);
        yh[b0 + j] = h; yl[b0 + j] = __float2bfloat16(o[j] - __bfloat162float(h));
    }
    #pragma unroll
    for (int j = 0; j < 4; j++) {
        __nv_bfloat16 h = __float2bfloat16(o[4 + j]);
        yh[b1 + j] = h; yl[b1 + j] = __float2bfloat16(o[4 + j] - __bfloat162float(h));
    }
}

// ======================= silu(g)*u on fused gu buffer -> bf16 hi/lo =========
__global__ void silu_conv2_k(const float* __restrict__ gu,
                             __nv_bfloat16* __restrict__ mh, __nv_bfloat16* __restrict__ ml)
{
    const int i = blockIdx.x * 256 + threadIdx.x;
    const int row = i >> 11;
    const int j4 = i & 2047;
    const float4 gv = ((const float4*)gu)[(size_t)row*4096 + j4];
    const float4 uv = ((const float4*)gu)[(size_t)row*4096 + 2048 + j4];
    float r[4];
    r[0] = gv.x / (1.f + __expf(-gv.x)) * uv.x;
    r[1] = gv.y / (1.f + __expf(-gv.y)) * uv.y;
    r[2] = gv.z / (1.f + __expf(-gv.z)) * uv.z;
    r[3] = gv.w / (1.f + __expf(-gv.w)) * uv.w;
    const size_t b = (size_t)row * INTER + j4 * 4;
    #pragma unroll
    for (int j = 0; j < 4; j++) {
        __nv_bfloat16 h = __float2bfloat16(r[j]);
        mh[b + j] = h; ml[b + j] = __float2bfloat16(r[j] - __bfloat162float(h));
    }
}

// ======================= launch =============================================
extern "C" void kernel_launch(void* const* d_in, const int* in_sizes, int n_in,
                              void* d_out, int out_size)
{
    const float* hidden = (const float*)d_in[0];
    const float* wq  = (const float*)d_in[1];
    const float* wk  = (const float*)d_in[2];
    const float* wv  = (const float*)d_in[3];
    const float* wo  = (const float*)d_in[4];
    const float* wg  = (const float*)d_in[5];
    const float* wu  = (const float*)d_in[6];
    const float* wd  = (const float*)d_in[7];
    const float* ln1 = (const float*)d_in[8];
    const float* ln2 = (const float*)d_in[9];

    __nv_bfloat16 *pwqkv_h,*pwqkv_l,*pwo_h,*pwo_l,*pwgu_h,*pwgu_l,*pwd_h,*pwd_l;
    __nv_bfloat16 *px_h,*px_l,*pat_h,*pat_l,*pm_h,*pm_l;
    __nv_bfloat16 *pqkv_h,*pqkv_l,*pvt_h,*pvt_l;
    float *h1,*gu;
    cudaGetSymbolAddress((void**)&pwqkv_h, w_qkv_hi); cudaGetSymbolAddress((void**)&pwqkv_l, w_qkv_lo);
    cudaGetSymbolAddress((void**)&pwo_h,   w_o_hi);   cudaGetSymbolAddress((void**)&pwo_l,   w_o_lo);
    cudaGetSymbolAddress((void**)&pwgu_h,  w_gu_hi);  cudaGetSymbolAddress((void**)&pwgu_l,  w_gu_lo);
    cudaGetSymbolAddress((void**)&pwd_h,   w_d_hi);   cudaGetSymbolAddress((void**)&pwd_l,   w_d_lo);
    cudaGetSymbolAddress((void**)&px_h,  a_x_hi);  cudaGetSymbolAddress((void**)&px_l,  a_x_lo);
    cudaGetSymbolAddress((void**)&pat_h, a_at_hi); cudaGetSymbolAddress((void**)&pat_l, a_at_lo);
    cudaGetSymbolAddress((void**)&pm_h,  a_m_hi);  cudaGetSymbolAddress((void**)&pm_l,  a_m_lo);
    cudaGetSymbolAddress((void**)&pqkv_h, qkv_hi); cudaGetSymbolAddress((void**)&pqkv_l, qkv_lo);
    cudaGetSymbolAddress((void**)&pvt_h, vt_hi);   cudaGetSymbolAddress((void**)&pvt_l, vt_lo);
    cudaGetSymbolAddress((void**)&h1, s_h1);       cudaGetSymbolAddress((void**)&gu, s_gu);

    cudaFuncSetAttribute(gemm3bf<0>, cudaFuncAttributeMaxDynamicSharedMemorySize, GEMM_SMEM);
    cudaFuncSetAttribute(gemm3bf<1>, cudaFuncAttributeMaxDynamicSharedMemorySize, GEMM_SMEM);
    cudaFuncSetAttribute(gemm3bf<2>, cudaFuncAttributeMaxDynamicSharedMemorySize, GEMM_SMEM);
    cudaFuncSetAttribute(attn_mma_k, cudaFuncAttributeMaxDynamicSharedMemorySize, ATTN_SMEM);

    // weight transpose+split into fused buffers
    dim3 tb(32, 8);
    transconv_k<<<dim3(HID/32,  HID/32),  tb>>>(wq, pwqkv_h,                 pwqkv_l,                 HID, HID);
    transconv_k<<<dim3(HID/32,  HID/32),  tb>>>(wk, pwqkv_h + (size_t)HID*HID,   pwqkv_l + (size_t)HID*HID,   HID, HID);
    transconv_k<<<dim3(HID/32,  HID/32),  tb>>>(wv, pwqkv_h + (size_t)2*HID*HID, pwqkv_l + (size_t)2*HID*HID, HID, HID);
    transconv_k<<<dim3(HID/32,  HID/32),  tb>>>(wo, pwo_h, pwo_l, HID, HID);
    transconv_k<<<dim3(INTER/32,HID/32),  tb>>>(wg, pwgu_h,                    pwgu_l,                    HID, INTER);
    transconv_k<<<dim3(INTER/32,HID/32),  tb>>>(wu, pwgu_h + (size_t)INTER*HID, pwgu_l + (size_t)INTER*HID, HID, INTER);
    transconv_k<<<dim3(HID/32,  INTER/32),tb>>>(wd, pwd_h, pwd_l, INTER, HID);

    // 1) rmsnorm -> bf16 hi/lo
    rmsnorm_conv_k<<<MTOK, 256>>>(hidden, ln1, px_h, px_l);

    // 2) fused QKV projection (Q cols scaled by 1/sqrt(d)), bf16 hi/lo out
    const float sc = 0.08838834764831845f;
    gemm3bf<2><<<dim3(3*HID/128, MTOK/128), 256, GEMM_SMEM>>>(
        px_h, px_l, pwqkv_h, pwqkv_l, nullptr, nullptr,
        pqkv_h, pqkv_l, sc, HID, MTOK, 3*HID, HID);

    // V transpose (hi/lo bf16)
    vtrans_bf_k<<<dim3(64, 4, 32), tb>>>(pqkv_h, pqkv_l, pvt_h, pvt_l);

    // 3) tensor-core attention -> bf16 hi/lo
    attn_mma_k<<<dim3(16, 16, 2), 256, ATTN_SMEM>>>(pqkv_h, pqkv_l, pvt_h, pvt_l,
                                                    pat_h, pat_l);

    // 4) O-proj + residual
    gemm3bf<1><<<dim3(HID/128, MTOK/128), 256, GEMM_SMEM>>>(
        pat_h, pat_l, pwo_h, pwo_l, hidden, h1,
        nullptr, nullptr, 1.f, 0, MTOK, HID, HID);

    // 5) rmsnorm2 -> bf16 hi/lo
    rmsnorm_conv_k<<<MTOK, 256>>>(h1, ln2, px_h, px_l);

    // 6) fused gate+up GEMM (N=16384), fp32 out
    gemm3bf<0><<<dim3(2*INTER/128, MTOK/128), 256, GEMM_SMEM>>>(
        px_h, px_l, pwgu_h, pwgu_l, nullptr, gu,
        nullptr, nullptr, 1.f, 0, MTOK, 2*INTER, HID);

    // silu(g)*u -> bf16 hi/lo
    silu_conv2_k<<<(MTOK*INTER/4 + 255)/256, 256>>>(gu, pm_h, pm_l);

    // down-proj + residual -> d_out
    gemm3bf<1><<<dim3(HID/128, MTOK/128), 256, GEMM_SMEM>>>(
        pm_h, pm_l, pwd_h, pwd_l, h1, (float*)d_out,
        nullptr, nullptr, 1.f, 0, MTOK, HID, INTER);
}

// round 8
// speedup vs baseline: 1.1700x; 1.0875x over previous
#include <cuda_runtime.h>
#include <cuda_bf16.h>
#include <math.h>
#include <stdint.h>

#define MTOK 4096      // B*S
#define HID  2048
#define INTER 8192

// ======================= device scratch (no allocations) ====================
__device__ __nv_bfloat16 w_q_hi[HID*HID],  w_q_lo[HID*HID];
__device__ __nv_bfloat16 w_k_hi[HID*HID],  w_k_lo[HID*HID];
__device__ __nv_bfloat16 w_v_hi[HID*HID],  w_v_lo[HID*HID];
__device__ __nv_bfloat16 w_o_hi[HID*HID],  w_o_lo[HID*HID];
__device__ __nv_bfloat16 w_g_hi[(size_t)INTER*HID], w_g_lo[(size_t)INTER*HID];
__device__ __nv_bfloat16 w_u_hi[(size_t)INTER*HID], w_u_lo[(size_t)INTER*HID];
__device__ __nv_bfloat16 w_d_hi[(size_t)HID*INTER], w_d_lo[(size_t)HID*INTER];
__device__ __nv_bfloat16 a_x_hi[MTOK*HID],  a_x_lo[MTOK*HID];
__device__ __nv_bfloat16 a_at_hi[MTOK*HID], a_at_lo[MTOK*HID];
__device__ __nv_bfloat16 a_m_hi[(size_t)MTOK*INTER], a_m_lo[(size_t)MTOK*INTER];
__device__ __nv_bfloat16 q_bhi[MTOK*HID], q_blo[MTOK*HID];
__device__ __nv_bfloat16 k_bhi[MTOK*HID], k_blo[MTOK*HID];
__device__ __nv_bfloat16 vt_hi[MTOK*HID], vt_lo[MTOK*HID];   // [b*16+h][hd][kv]
__device__ float s_v [MTOK*HID];
__device__ float s_h1[MTOK*HID];
__device__ float s_g [(size_t)MTOK*INTER];
__device__ float s_u [(size_t)MTOK*INTER];

// ======================= helpers ============================================
__device__ __forceinline__ uint32_t smem_u32(const void* p) {
    uint32_t a;
    asm("{ .reg .u64 t; cvta.to.shared.u64 t, %1; cvt.u32.u64 %0, t; }" : "=r"(a) : "l"(p));
    return a;
}
__device__ __forceinline__ void cp16(uint32_t s, const void* g) {
    asm volatile("cp.async.cg.shared.global [%0], [%1], 16;" :: "r"(s), "l"(g));
}
#define CP_COMMIT() asm volatile("cp.async.commit_group;")
#define CP_WAIT(N)  asm volatile("cp.async.wait_group %0;" :: "n"(N))

__device__ __forceinline__ void mma_bf16(float* c, const uint32_t* a, const uint32_t* b) {
    asm volatile(
        "mma.sync.aligned.m16n8k16.row.col.f32.bf16.bf16.f32 "
        "{%0,%1,%2,%3}, {%4,%5,%6,%7}, {%8,%9}, {%0,%1,%2,%3};"
        : "+f"(c[0]), "+f"(c[1]), "+f"(c[2]), "+f"(c[3])
        : "r"(a[0]), "r"(a[1]), "r"(a[2]), "r"(a[3]), "r"(b[0]), "r"(b[1]));
}
__device__ __forceinline__ void split2(float x, float y, uint32_t& hi, uint32_t& lo) {
    __nv_bfloat162 h;
    h.x = __float2bfloat16(x); h.y = __float2bfloat16(y);
    __nv_bfloat162 l;
    l.x = __float2bfloat16(x - __bfloat162float(h.x));
    l.y = __float2bfloat16(y - __bfloat162float(h.y));
    hi = *reinterpret_cast<uint32_t*>(&h);
    lo = *reinterpret_cast<uint32_t*>(&l);
}

// ======================= bf16x3 mma.sync GEMM ===============================
// OM: 0 = fp32 out, 1 = fp32 out + residual, 2 = bf16 hi/lo out (scaled)
// Block tile 256x128, BK=64, 256 threads (8 warps: 4 M x 2 N), warp tile 64x64.
// Double-buffered cp.async, 2 syncs/stage (round-4 pipeline).
#define RB    144
#define ATILE (256*RB)           // 36864 per split
#define BTILE (128*RB)           // 18432 per split
#define STG   (2*ATILE + 2*BTILE)  // 110592
#define GEMM_SMEM (2*STG)          // 221184

template<int OM>
__global__ __launch_bounds__(256) void gemm3bf(
    const __nv_bfloat16* __restrict__ Ahi, const __nv_bfloat16* __restrict__ Alo,
    const __nv_bfloat16* __restrict__ Bhi, const __nv_bfloat16* __restrict__ Blo,
    const float* __restrict__ R, float* __restrict__ C,
    __nv_bfloat16* __restrict__ Ch, __nv_bfloat16* __restrict__ Cl,
    float scale, int M, int N, int K)
{
    extern __shared__ char sm[];
    const uint32_t sbase = smem_u32(sm);

    const int tid = threadIdx.x;
    const int lane = tid & 31;
    const int wid = tid >> 5;
    const int g = lane >> 2, tig = lane & 3;
    const int warp_m = wid & 3;      // 0..3 -> 64 rows each
    const int warp_n = wid >> 2;     // 0..1 -> 64 cols each
    const int bm = blockIdx.y * 256;
    const int bn = blockIdx.x * 128;

    const int crow = tid >> 3;            // 0..31
    const int ccolB = (tid & 7) * 16;

    const int S = K >> 6;

    auto load_stage = [&](int s) {
        const uint32_t b = sbase + (uint32_t)(s & 1) * STG;
        const int k0 = s << 6;
        const size_t ga = ((size_t)(bm + crow) * K + k0) * 2 + ccolB;
        const size_t gb = ((size_t)(bn + crow) * K + k0) * 2 + ccolB;
        const size_t rstep = (size_t)32 * K * 2;
        const char* pah = (const char*)Ahi + ga;
        const char* pal = (const char*)Alo + ga;
        const char* pbh = (const char*)Bhi + gb;
        const char* pbl = (const char*)Blo + gb;
        // A: 256 rows (8 iters), B: 128 rows (4 iters)
        #pragma unroll
        for (int i = 0; i < 8; i++) {
            const uint32_t so = (uint32_t)((crow + 32*i) * RB + ccolB);
            cp16(b + so,         pah); pah += rstep;
            cp16(b + ATILE + so, pal); pal += rstep;
        }
        #pragma unroll
        for (int i = 0; i < 4; i++) {
            const uint32_t so = (uint32_t)((crow + 32*i) * RB + ccolB);
            cp16(b + 2*ATILE + so,         pbh); pbh += rstep;
            cp16(b + 2*ATILE + BTILE + so, pbl); pbl += rstep;
        }
        CP_COMMIT();
    };

    load_stage(0);
    if (S > 1) load_stage(1);

    float acc[4][8][4];
    #pragma unroll
    for (int mt = 0; mt < 4; mt++)
        #pragma unroll
        for (int nt = 0; nt < 8; nt++)
            #pragma unroll
            for (int e = 0; e < 4; e++) acc[mt][nt][e] = 0.f;

    const int arow0 = warp_m * 64 + g;
    const int brow0 = warp_n * 64 + g;

    for (int s = 0; s < S; ++s) {
        if (s + 1 < S) { CP_WAIT(1); } else { CP_WAIT(0); }
        __syncthreads();
        const char* b = sm + (size_t)(s & 1) * STG;

        #pragma unroll
        for (int ks = 0; ks < 4; ++ks) {
            const int kb = ks * 32 + tig * 4;

            uint32_t bhf[8][2], blf[8][2];
            #pragma unroll
            for (int nt = 0; nt < 8; nt++) {
                const char* rb = b + 2*ATILE + (brow0 + nt*8) * RB + kb;
                bhf[nt][0] = *(const uint32_t*)(rb);
                bhf[nt][1] = *(const uint32_t*)(rb + 16);
                blf[nt][0] = *(const uint32_t*)(rb + BTILE);
                blf[nt][1] = *(const uint32_t*)(rb + BTILE + 16);
            }

            #pragma unroll
            for (int mt = 0; mt < 4; mt++) {
                uint32_t ah[4], al[4];
                const char* ra = b + (arow0 + mt*16) * RB + kb;
                ah[0] = *(const uint32_t*)(ra);
                ah[1] = *(const uint32_t*)(ra + 8*RB);
                ah[2] = *(const uint32_t*)(ra + 16);
                ah[3] = *(const uint32_t*)(ra + 8*RB + 16);
                al[0] = *(const uint32_t*)(ra + ATILE);
                al[1] = *(const uint32_t*)(ra + ATILE + 8*RB);
                al[2] = *(const uint32_t*)(ra + ATILE + 16);
                al[3] = *(const uint32_t*)(ra + ATILE + 8*RB + 16);

                #pragma unroll
                for (int nt = 0; nt < 8; nt++)
                    mma_bf16(acc[mt][nt], ah, bhf[nt]);
                #pragma unroll
                for (int nt = 0; nt < 8; nt++)
                    mma_bf16(acc[mt][nt], ah, blf[nt]);
                #pragma unroll
                for (int nt = 0; nt < 8; nt++)
                    mma_bf16(acc[mt][nt], al, bhf[nt]);
            }
        }
        __syncthreads();
        if (s + 2 < S) load_stage(s + 2);
    }

    const int row0 = bm + warp_m*64 + g;
    const int col0 = bn + warp_n*64 + tig*2;
    #pragma unroll
    for (int mt = 0; mt < 4; mt++) {
        #pragma unroll
        for (int nt = 0; nt < 8; nt++) {
            const int r = row0 + mt*16;
            const int c = col0 + nt*8;
            if (OM == 2) {
                uint32_t h0, l0u, h1, l1u;
                split2(acc[mt][nt][0]*scale, acc[mt][nt][1]*scale, h0, l0u);
                split2(acc[mt][nt][2]*scale, acc[mt][nt][3]*scale, h1, l1u);
                *(uint32_t*)(Ch + (size_t)r * N + c)     = h0;
                *(uint32_t*)(Cl + (size_t)r * N + c)     = l0u;
                *(uint32_t*)(Ch + (size_t)(r+8) * N + c) = h1;
                *(uint32_t*)(Cl + (size_t)(r+8) * N + c) = l1u;
            } else {
                float2 v0 = make_float2(acc[mt][nt][0], acc[mt][nt][1]);
                float2 v1 = make_float2(acc[mt][nt][2], acc[mt][nt][3]);
                if (OM == 1) {
                    const float2 r0 = *(const float2*)(R + (size_t)r * N + c);
                    const float2 r1 = *(const float2*)(R + (size_t)(r+8) * N + c);
                    v0.x += r0.x; v0.y += r0.y;
                    v1.x += r1.x; v1.y += r1.y;
                }
                *(float2*)(C + (size_t)r * N + c)     = v0;
                *(float2*)(C + (size_t)(r+8) * N + c) = v1;
            }
        }
    }
}

// ======================= tensor-core causal flash attention =================
// (verbatim round 4)
#define RBQ 272
#define RBV 144
#define QT_BYTES (128*RBQ)
#define KT_BYTES (64*RBQ)
#define VT_BYTES (128*RBV)
#define STAGE_B  (2*KT_BYTES + 2*VT_BYTES)
#define ATTN_SMEM (2*QT_BYTES + 2*STAGE_B)

__global__ __launch_bounds__(256) void attn_mma_k(
    const __nv_bfloat16* __restrict__ qh, const __nv_bfloat16* __restrict__ ql,
    const __nv_bfloat16* __restrict__ kh, const __nv_bfloat16* __restrict__ kl,
    const __nv_bfloat16* __restrict__ vh, const __nv_bfloat16* __restrict__ vl,
    __nv_bfloat16* __restrict__ Oh, __nv_bfloat16* __restrict__ Ol)
{
    extern __shared__ char sm[];
    const uint32_t sb = smem_u32(sm);

    const int tid = threadIdx.x, lane = tid & 31, wid = tid >> 5;
    const int g = lane >> 2, tig = lane & 3;
    const int qt = 15 - blockIdx.x, h = blockIdx.y, b = blockIdx.z;
    const int ntiles = 2 * (qt + 1);

    {
        const size_t gq = ((size_t)(b*2048 + qt*128) * 2048 + h*128) * 2;
        #pragma unroll
        for (int i = 0; i < 16; i++) {
            const int c = tid + i*256;
            const int t = c >> 11;
            const int cc = c & 2047;
            const int row = cc >> 4, col = cc & 15;
            const char* gp = (const char*)(t ? ql : qh) + gq + (size_t)row*4096 + col*16;
            cp16(sb + (t ? QT_BYTES : 0) + row*RBQ + col*16, gp);
        }
        CP_COMMIT();
    }

    auto load_stage = [&](int kt) {
        const uint32_t base = sb + 2*QT_BYTES + (uint32_t)(kt & 1) * STAGE_B;
        const size_t gk = ((size_t)(b*2048 + kt*64) * 2048 + h*128) * 2;
        const size_t gv = (((size_t)((b*16 + h)*128)) * 2048 + kt*64) * 2;
        #pragma unroll
        for (int i = 0; i < 16; i++) {
            const int c = tid + i*256;
            const int sel = c >> 10;
            const int cc = c & 1023;
            if (sel < 2) {
                const int row = cc >> 4, col = cc & 15;
                const char* gp = (const char*)(sel ? kl : kh) + gk + (size_t)row*4096 + col*16;
                cp16(base + (sel ? KT_BYTES : 0) + row*RBQ + col*16, gp);
            } else {
                const int row = cc >> 3, col = cc & 7;
                const char* gp = (const char*)(sel == 3 ? vl : vh) + gv + (size_t)row*4096 + col*16;
                cp16(base + 2*KT_BYTES + (sel == 3 ? VT_BYTES : 0) + row*RBV + col*16, gp);
            }
        }
        CP_COMMIT();
    };

    load_stage(0);
    load_stage(1);

    float accO[16][4];
    #pragma unroll
    for (int nt = 0; nt < 16; nt++)
        #pragma unroll
        for (int e = 0; e < 4; e++) accO[nt][e] = 0.f;
    float m0 = -INFINITY, m1 = -INFINITY, l0 = 0.f, l1 = 0.f;

    const int row0 = wid * 16;
    const int qrow0 = qt*128 + row0 + g;

    for (int s = 0; s < ntiles; s++) {
        if (s + 1 < ntiles) { CP_WAIT(1); } else { CP_WAIT(0); }
        __syncthreads();
        const char* stg = sm + 2*QT_BYTES + (size_t)(s & 1) * STAGE_B;

        float accS[8][4];
        #pragma unroll
        for (int nt = 0; nt < 8; nt++)
            #pragma unroll
            for (int e = 0; e < 4; e++) accS[nt][e] = 0.f;

        #pragma unroll
        for (int ks = 0; ks < 8; ks++) {
            const int kb = ks*32 + tig*4;
            uint32_t ah[4], al[4], bh2[8][2], bl2[8][2];
            const char* ra = sm + (row0 + g)*RBQ + kb;
            ah[0] = *(const uint32_t*)(ra);
            ah[1] = *(const uint32_t*)(ra + 8*RBQ);
            ah[2] = *(const uint32_t*)(ra + 16);
            ah[3] = *(const uint32_t*)(ra + 8*RBQ + 16);
            al[0] = *(const uint32_t*)(ra + QT_BYTES);
            al[1] = *(const uint32_t*)(ra + QT_BYTES + 8*RBQ);
            al[2] = *(const uint32_t*)(ra + QT_BYTES + 16);
            al[3] = *(const uint32_t*)(ra + QT_BYTES + 8*RBQ + 16);
            #pragma unroll
            for (int nt = 0; nt < 8; nt++) {
                const char* rb = stg + (nt*8 + g)*RBQ + kb;
                bh2[nt][0] = *(const uint32_t*)(rb);
                bh2[nt][1] = *(const uint32_t*)(rb + 16);
                bl2[nt][0] = *(const uint32_t*)(rb + KT_BYTES);
                bl2[nt][1] = *(const uint32_t*)(rb + KT_BYTES + 16);
            }
            #pragma unroll
            for (int nt = 0; nt < 8; nt++) mma_bf16(accS[nt], ah, bh2[nt]);
            #pragma unroll
            for (int nt = 0; nt < 8; nt++) mma_bf16(accS[nt], ah, bl2[nt]);
            #pragma unroll
            for (int nt = 0; nt < 8; nt++) mma_bf16(accS[nt], al, bh2[nt]);
        }

        if (s >= ntiles - 2) {
            #pragma unroll
            for (int nt = 0; nt < 8; nt++) {
                const int col = s*64 + nt*8 + tig*2;
                if (col     > qrow0)     accS[nt][0] = -INFINITY;
                if (col + 1 > qrow0)     accS[nt][1] = -INFINITY;
                if (col     > qrow0 + 8) accS[nt][2] = -INFINITY;
                if (col + 1 > qrow0 + 8) accS[nt][3] = -INFINITY;
            }
        }

        float mt0 = -INFINITY, mt1 = -INFINITY;
        #pragma unroll
        for (int nt = 0; nt < 8; nt++) {
            mt0 = fmaxf(mt0, fmaxf(accS[nt][0], accS[nt][1]));
            mt1 = fmaxf(mt1, fmaxf(accS[nt][2], accS[nt][3]));
        }
        mt0 = fmaxf(mt0, __shfl_xor_sync(0xffffffffu, mt0, 1));
        mt0 = fmaxf(mt0, __shfl_xor_sync(0xffffffffu, mt0, 2));
        mt1 = fmaxf(mt1, __shfl_xor_sync(0xffffffffu, mt1, 1));
        mt1 = fmaxf(mt1, __shfl_xor_sync(0xffffffffu, mt1, 2));

        const float mn0 = fmaxf(m0, mt0), mn1 = fmaxf(m1, mt1);
        const float sc0 = __expf(m0 - mn0), sc1 = __expf(m1 - mn1);
        m0 = mn0; m1 = mn1;

        float rs0 = 0.f, rs1 = 0.f;
        #pragma unroll
        for (int nt = 0; nt < 8; nt++) {
            accS[nt][0] = __expf(accS[nt][0] - mn0);
            accS[nt][1] = __expf(accS[nt][1] - mn0);
            accS[nt][2] = __expf(accS[nt][2] - mn1);
            accS[nt][3] = __expf(accS[nt][3] - mn1);
            rs0 += accS[nt][0] + accS[nt][1];
            rs1 += accS[nt][2] + accS[nt][3];
        }
        rs0 += __shfl_xor_sync(0xffffffffu, rs0, 1);
        rs0 += __shfl_xor_sync(0xffffffffu, rs0, 2);
        rs1 += __shfl_xor_sync(0xffffffffu, rs1, 1);
        rs1 += __shfl_xor_sync(0xffffffffu, rs1, 2);
        l0 = l0*sc0 + rs0;
        l1 = l1*sc1 + rs1;

        #pragma unroll
        for (int nt = 0; nt < 16; nt++) {
            accO[nt][0] *= sc0; accO[nt][1] *= sc0;
            accO[nt][2] *= sc1; accO[nt][3] *= sc1;
        }

        #pragma unroll
        for (int kk = 0; kk < 4; kk++) {
            uint32_t ph[4], pl[4];
            split2(accS[2*kk][0],   accS[2*kk][1],   ph[0], pl[0]);
            split2(accS[2*kk][2],   accS[2*kk][3],   ph[1], pl[1]);
            split2(accS[2*kk+1][0], accS[2*kk+1][1], ph[2], pl[2]);
            split2(accS[2*kk+1][2], accS[2*kk+1][3], ph[3], pl[3]);
            const int kb = kk*32 + tig*4;
            #pragma unroll
            for (int nt = 0; nt < 16; nt++) {
                const char* rv = stg + 2*KT_BYTES + (nt*8 + g)*RBV + kb;
                uint32_t vbh[2], vbl[2];
                vbh[0] = *(const uint32_t*)(rv);
                vbh[1] = *(const uint32_t*)(rv + 16);
                vbl[0] = *(const uint32_t*)(rv + VT_BYTES);
                vbl[1] = *(const uint32_t*)(rv + VT_BYTES + 16);
                mma_bf16(accO[nt], ph, vbh);
                mma_bf16(accO[nt], ph, vbl);
                mma_bf16(accO[nt], pl, vbh);
            }
        }

        __syncthreads();
        if (s + 2 < ntiles) load_stage(s + 2);
    }

    const float inv0 = 1.f / l0, inv1 = 1.f / l1;
    const size_t ob = ((size_t)(b*2048 + qt*128 + row0 + g)) * 2048 + h*128;
    #pragma unroll
    for (int nt = 0; nt < 16; nt++) {
        const int c = nt*8 + tig*2;
        uint32_t h0, l0u, h1, l1u;
        split2(accO[nt][0]*inv0, accO[nt][1]*inv0, h0, l0u);
        split2(accO[nt][2]*inv1, accO[nt][3]*inv1, h1, l1u);
        *(uint32_t*)(Oh + ob + c)           = h0;
        *(uint32_t*)(Ol + ob + c)           = l0u;
        *(uint32_t*)(Oh + ob + 8*2048 + c)  = h1;
        *(uint32_t*)(Ol + ob + 8*2048 + c)  = l1u;
    }
}

// ======================= weight transpose + split ==========================
__global__ void transconv_k(const float* __restrict__ W,
                            __nv_bfloat16* __restrict__ Thi, __nv_bfloat16* __restrict__ Tlo,
                            int K, int N)
{
    __shared__ float t[32][33];
    const int n0 = blockIdx.x * 32, k0 = blockIdx.y * 32;
    const int tx = threadIdx.x, ty = threadIdx.y;
    #pragma unroll
    for (int i = ty; i < 32; i += 8)
        t[i][tx] = W[(size_t)(k0 + i) * N + n0 + tx];
    __syncthreads();
    #pragma unroll
    for (int i = ty; i < 32; i += 8) {
        const float v = t[tx][i];
        const __nv_bfloat16 hi = __float2bfloat16(v);
        const __nv_bfloat16 lo = __float2bfloat16(v - __bfloat162float(hi));
        const size_t o = (size_t)(n0 + i) * K + k0 + tx;
        Thi[o] = hi; Tlo[o] = lo;
    }
}

// ======================= V transpose: [tok][hid] f32 -> [bh][hd][kv] bf16 ===
__global__ void vtrans_k(const float* __restrict__ V,
                         __nv_bfloat16* __restrict__ Th, __nv_bfloat16* __restrict__ Tl)
{
    __shared__ float t[32][33];
    const int kv0 = blockIdx.x * 32, hd0 = blockIdx.y * 32, bh = blockIdx.z;
    const int b = bh >> 4, h = bh & 15;
    const int tx = threadIdx.x, ty = threadIdx.y;
    #pragma unroll
    for (int i = ty; i < 32; i += 8)
        t[i][tx] = V[(size_t)(b*2048 + kv0 + i) * 2048 + h*128 + hd0 + tx];
    __syncthreads();
    #pragma unroll
    for (int i = ty; i < 32; i += 8) {
        const float v = t[tx][i];
        const __nv_bfloat16 hi = __float2bfloat16(v);
        const __nv_bfloat16 lo = __float2bfloat16(v - __bfloat162float(hi));
        const size_t o = ((size_t)(bh*128 + hd0 + i)) * 2048 + kv0 + tx;
        Th[o] = hi; Tl[o] = lo;
    }
}

// ======================= RMSNorm -> bf16 hi/lo ==============================
__global__ __launch_bounds__(256) void rmsnorm_conv_k(
    const float* __restrict__ x, const float* __restrict__ w,
    __nv_bfloat16* __restrict__ yh, __nv_bfloat16* __restrict__ yl)
{
    const int row = blockIdx.x;
    const float4* xr = (const float4*)(x + (size_t)row * HID);
    const float4* w4 = (const float4*)w;

    float4 v0 = xr[threadIdx.x];
    float4 v1 = xr[threadIdx.x + 256];
    float ss = v0.x*v0.x + v0.y*v0.y + v0.z*v0.z + v0.w*v0.w
             + v1.x*v1.x + v1.y*v1.y + v1.z*v1.z + v1.w*v1.w;
    #pragma unroll
    for (int off = 16; off > 0; off >>= 1) ss += __shfl_xor_sync(0xffffffffu, ss, off);

    __shared__ float red[8]; __shared__ float s_inv;
    if ((threadIdx.x & 31) == 0) red[threadIdx.x >> 5] = ss;
    __syncthreads();
    if (threadIdx.x == 0) {
        float t = 0.f;
        #pragma unroll
        for (int i = 0; i < 8; i++) t += red[i];
        s_inv = rsqrtf(t * (1.f / (float)HID) + 1e-6f);
    }
    __syncthreads();
    const float inv = s_inv;

    const float4 w0 = w4[threadIdx.x], w1 = w4[threadIdx.x + 256];
    float o[8] = { v0.x*inv*w0.x, v0.y*inv*w0.y, v0.z*inv*w0.z, v0.w*inv*w0.w,
                   v1.x*inv*w1.x, v1.y*inv*w1.y, v1.z*inv*w1.z, v1.w*inv*w1.w };
    const size_t b0 = (size_t)row * HID + threadIdx.x * 4;
    const size_t b1 = (size_t)row * HID + (threadIdx.x + 256) * 4;
    #pragma unroll
    for (int j = 0; j < 4; j++) {
        __nv_bfloat16 h = __float2bfloat16(o[j]);
        yh[b0 + j] = h; yl[b0 + j] = __float2bfloat16(o[j] - __bfloat162float(h));
    }
    #pragma unroll
    for (int j = 0; j < 4; j++) {
        __nv_bfloat16 h = __float2bfloat16(o[4 + j]);
        yh[b1 + j] = h; yl[b1 + j] = __float2bfloat16(o[4 + j] - __bfloat162float(h));
    }
}

// ======================= silu(g)*u -> bf16 hi/lo ============================
__global__ void silu_conv_k(const float* __restrict__ g, const float* __restrict__ u,
                            __nv_bfloat16* __restrict__ mh, __nv_bfloat16* __restrict__ ml,
                            int n4)
{
    int i = blockIdx.x * 256 + threadIdx.x;
    if (i < n4) {
        float4 gv = ((const float4*)g)[i];
        float4 uv = ((const float4*)u)[i];
        float r[4];
        r[0] = gv.x / (1.f + __expf(-gv.x)) * uv.x;
        r[1] = gv.y / (1.f + __expf(-gv.y)) * uv.y;
        r[2] = gv.z / (1.f + __expf(-gv.z)) * uv.z;
        r[3] = gv.w / (1.f + __expf(-gv.w)) * uv.w;
        const size_t b = (size_t)i * 4;
        #pragma unroll
        for (int j = 0; j < 4; j++) {
            __nv_bfloat16 h = __float2bfloat16(r[j]);
            mh[b + j] = h; ml[b + j] = __float2bfloat16(r[j] - __bfloat162float(h));
        }
    }
}

// ======================= launch =============================================
extern "C" void kernel_launch(void* const* d_in, const int* in_sizes, int n_in,
                              void* d_out, int out_size)
{
    const float* hidden = (const float*)d_in[0];
    const float* wq  = (const float*)d_in[1];
    const float* wk  = (const float*)d_in[2];
    const float* wv  = (const float*)d_in[3];
    const float* wo  = (const float*)d_in[4];
    const float* wg  = (const float*)d_in[5];
    const float* wu  = (const float*)d_in[6];
    const float* wd  = (const float*)d_in[7];
    const float* ln1 = (const float*)d_in[8];
    const float* ln2 = (const float*)d_in[9];

    __nv_bfloat16 *pwq_h,*pwq_l,*pwk_h,*pwk_l,*pwv_h,*pwv_l,*pwo_h,*pwo_l;
    __nv_bfloat16 *pwg_h,*pwg_l,*pwu_h,*pwu_l,*pwd_h,*pwd_l;
    __nv_bfloat16 *px_h,*px_l,*pat_h,*pat_l,*pm_h,*pm_l;
    __nv_bfloat16 *pq_h,*pq_l,*pk_h,*pk_l,*pvt_h,*pvt_l;
    float *v,*h1,*g,*u;
    cudaGetSymbolAddress((void**)&pwq_h, w_q_hi); cudaGetSymbolAddress((void**)&pwq_l, w_q_lo);
    cudaGetSymbolAddress((void**)&pwk_h, w_k_hi); cudaGetSymbolAddress((void**)&pwk_l, w_k_lo);
    cudaGetSymbolAddress((void**)&pwv_h, w_v_hi); cudaGetSymbolAddress((void**)&pwv_l, w_v_lo);
    cudaGetSymbolAddress((void**)&pwo_h, w_o_hi); cudaGetSymbolAddress((void**)&pwo_l, w_o_lo);
    cudaGetSymbolAddress((void**)&pwg_h, w_g_hi); cudaGetSymbolAddress((void**)&pwg_l, w_g_lo);
    cudaGetSymbolAddress((void**)&pwu_h, w_u_hi); cudaGetSymbolAddress((void**)&pwu_l, w_u_lo);
    cudaGetSymbolAddress((void**)&pwd_h, w_d_hi); cudaGetSymbolAddress((void**)&pwd_l, w_d_lo);
    cudaGetSymbolAddress((void**)&px_h,  a_x_hi); cudaGetSymbolAddress((void**)&px_l,  a_x_lo);
    cudaGetSymbolAddress((void**)&pat_h, a_at_hi);cudaGetSymbolAddress((void**)&pat_l, a_at_lo);
    cudaGetSymbolAddress((void**)&pm_h,  a_m_hi); cudaGetSymbolAddress((void**)&pm_l,  a_m_lo);
    cudaGetSymbolAddress((void**)&pq_h,  q_bhi);  cudaGetSymbolAddress((void**)&pq_l,  q_blo);
    cudaGetSymbolAddress((void**)&pk_h,  k_bhi);  cudaGetSymbolAddress((void**)&pk_l,  k_blo);
    cudaGetSymbolAddress((void**)&pvt_h, vt_hi);  cudaGetSymbolAddress((void**)&pvt_l, vt_lo);
    cudaGetSymbolAddress((void**)&v,  s_v);  cudaGetSymbolAddress((void**)&h1, s_h1);
    cudaGetSymbolAddress((void**)&g,  s_g);  cudaGetSymbolAddress((void**)&u,  s_u);

    cudaFuncSetAttribute(gemm3bf<0>, cudaFuncAttributeMaxDynamicSharedMemorySize, GEMM_SMEM);
    cudaFuncSetAttribute(gemm3bf<1>, cudaFuncAttributeMaxDynamicSharedMemorySize, GEMM_SMEM);
    cudaFuncSetAttribute(gemm3bf<2>, cudaFuncAttributeMaxDynamicSharedMemorySize, GEMM_SMEM);
    cudaFuncSetAttribute(attn_mma_k, cudaFuncAttributeMaxDynamicSharedMemorySize, ATTN_SMEM);

    // weight transpose+split
    dim3 tb(32, 8);
    transconv_k<<<dim3(HID/32,  HID/32),  tb>>>(wq, pwq_h, pwq_l, HID, HID);
    transconv_k<<<dim3(HID/32,  HID/32),  tb>>>(wk, pwk_h, pwk_l, HID, HID);
    transconv_k<<<dim3(HID/32,  HID/32),  tb>>>(wv, pwv_h, pwv_l, HID, HID);
    transconv_k<<<dim3(HID/32,  HID/32),  tb>>>(wo, pwo_h, pwo_l, HID, HID);
    transconv_k<<<dim3(INTER/32,HID/32),  tb>>>(wg, pwg_h, pwg_l, HID, INTER);
    transconv_k<<<dim3(INTER/32,HID/32),  tb>>>(wu, pwu_h, pwu_l, HID, INTER);
    transconv_k<<<dim3(HID/32,  INTER/32),tb>>>(wd, pwd_h, pwd_l, INTER, HID);

    // 1) rmsnorm -> bf16 hi/lo
    rmsnorm_conv_k<<<MTOK, 256>>>(hidden, ln1, px_h, px_l);

    // 2) QKV projections (block 256x128)
    const float sc = 0.08838834764831845f;
    dim3 gHH(HID/128, MTOK/256);   // (16, 16)
    gemm3bf<2><<<gHH, 256, GEMM_SMEM>>>(px_h, px_l, pwq_h, pwq_l, nullptr, nullptr,
                                        pq_h, pq_l, sc, MTOK, HID, HID);
    gemm3bf<2><<<gHH, 256, GEMM_SMEM>>>(px_h, px_l, pwk_h, pwk_l, nullptr, nullptr,
                                        pk_h, pk_l, 1.f, MTOK, HID, HID);
    gemm3bf<0><<<gHH, 256, GEMM_SMEM>>>(px_h, px_l, pwv_h, pwv_l, nullptr, v,
                                        nullptr, nullptr, 1.f, MTOK, HID, HID);
    vtrans_k<<<dim3(64, 4, 32), tb>>>(v, pvt_h, pvt_l);

    // 3) tensor-core attention -> bf16 hi/lo
    attn_mma_k<<<dim3(16, 16, 2), 256, ATTN_SMEM>>>(pq_h, pq_l, pk_h, pk_l,
                                                    pvt_h, pvt_l, pat_h, pat_l);

    // 4) O-proj + residual
    gemm3bf<1><<<gHH, 256, GEMM_SMEM>>>(pat_h, pat_l, pwo_h, pwo_l, hidden, h1,
                                        nullptr, nullptr, 1.f, MTOK, HID, HID);

    // 5) rmsnorm2 -> bf16 hi/lo
    rmsnorm_conv_k<<<MTOK, 256>>>(h1, ln2, px_h, px_l);

    // 6) MLP
    dim3 gHI(INTER/128, MTOK/256); // (64, 16)
    gemm3bf<0><<<gHI, 256, GEMM_SMEM>>>(px_h, px_l, pwg_h, pwg_l, nullptr, g,
                                        nullptr, nullptr, 1.f, MTOK, INTER, HID);
    gemm3bf<0><<<gHI, 256, GEMM_SMEM>>>(px_h, px_l, pwu_h, pwu_l, nullptr, u,
                                        nullptr, nullptr, 1.f, MTOK, INTER, HID);

    const int n4 = (int)(((size_t)MTOK * INTER) / 4);
    silu_conv_k<<<(n4 + 255)/256, 256>>>(g, u, pm_h, pm_l, n4);

    gemm3bf<1><<<gHH, 256, GEMM_SMEM>>>(pm_h, pm_l, pwd_h, pwd_l, h1, (float*)d_out,
                                        nullptr, nullptr, 1.f, MTOK, HID, INTER);
}